// round 2
// baseline (speedup 1.0000x reference)
#include <cuda_runtime.h>

#define NB   64
#define NC   256
#define NH   64
#define NW   64
#define NP   4096        // H*W
#define NE   4
#define NO   65          // OUT = CELL*CELL+1
#define NOP  72          // padded OUT (multiple of 8)
#define NCH  16          // C chunk for GEMM smem

// ---------------- device scratch (no allocations allowed) ----------------
__device__ float  g_pooled[NB * NC];
__device__ int    g_idx[NB];
__device__ float2 g_part[NO * NB];
__device__ float  g_scale[NO];
__device__ float  g_shift[NO];

// ---------------- K1: pooled[b][c] = mean over pixels of relu(x) ----------------
__global__ void k1_pool(const float* __restrict__ x) {
    int plane = blockIdx.x;                       // b*NC + c
    const float4* base = (const float4*)(x + (long)plane * NP);
    float s = 0.f;
    #pragma unroll
    for (int i = 0; i < 8; i++) {
        float4 v = base[threadIdx.x + 128 * i];
        s += fmaxf(v.x, 0.f) + fmaxf(v.y, 0.f) + fmaxf(v.z, 0.f) + fmaxf(v.w, 0.f);
    }
    #pragma unroll
    for (int o = 16; o; o >>= 1) s += __shfl_xor_sync(0xffffffffu, s, o);
    __shared__ float red[4];
    if ((threadIdx.x & 31) == 0) red[threadIdx.x >> 5] = s;
    __syncthreads();
    if (threadIdx.x == 0)
        g_pooled[plane] = (red[0] + red[1] + red[2] + red[3]) * (1.f / NP);
}

// ---------------- K2: gate logits -> argmax expert, lb_loss ----------------
__global__ void k2_gate(const float* __restrict__ w_gate,
                        const float* __restrict__ b_gate,
                        float* __restrict__ loss_out) {
    int b = threadIdx.x;                          // 64 threads
    float lg[NE];
    #pragma unroll
    for (int e = 0; e < NE; e++) lg[e] = b_gate[e];
    const float* pr = g_pooled + b * NC;
    for (int c = 0; c < NC; c++) {
        float pv = pr[c];
        #pragma unroll
        for (int e = 0; e < NE; e++) lg[e] += pv * w_gate[c * NE + e];
    }
    int best = 0; float bv = lg[0];
    #pragma unroll
    for (int e = 1; e < NE; e++)
        if (lg[e] > bv) { bv = lg[e]; best = e; }   // first max on ties, like argmax
    g_idx[b] = best;

    __shared__ int sidx[NB];
    sidx[b] = best;
    __syncthreads();
    if (b == 0) {
        int cnt[NE] = {0, 0, 0, 0};
        for (int i = 0; i < NB; i++) cnt[sidx[i]]++;
        float u[NE]; float s = 0.f;
        #pragma unroll
        for (int e = 0; e < NE; e++) { u[e] = (float)cnt[e] / (float)NB + 1e-6f; s += u[e]; }
        float lb = 0.f;
        #pragma unroll
        for (int e = 0; e < NE; e++) {
            float uu = u[e] / s;
            lb += uu * (logf(uu) - logf(0.25f));
        }
        loss_out[0] = lb;
    }
}

// ---------------- K3: per-batch expert GEMM with packed f32x2 FMA ----------------
// y[b][o][p] = sum_c relu(x[b][c][p]) * W[e][c][o] + bias[e][o]  (unnormalized, written to logits region)
__global__ __launch_bounds__(256, 2) void k3_gemm(
    const float* __restrict__ x,
    const float* __restrict__ w_experts,
    const float* __restrict__ b_experts,
    float* __restrict__ ylog) {
    __shared__ float  xs[NCH][256];
    __shared__ float2 ws[NCH][NOP];   // weight duplicated into both f32x2 halves

    int b  = blockIdx.y;
    int p0 = blockIdx.x * 256;
    int tid = threadIdx.x;
    int tx = tid & 31;                // lane -> pixel pairs
    int ty = tid >> 5;                // warp -> out group (constant across warp -> broadcast LDS)
    int e = g_idx[b];

    const float* xb = x + ((long)b * NC) * NP + p0;
    const float* wb = w_experts + (long)e * NC * NO;

    unsigned long long acc[4][9];
    #pragma unroll
    for (int k = 0; k < 4; k++)
        #pragma unroll
        for (int j = 0; j < 9; j++) acc[k][j] = 0ull;

    for (int c0 = 0; c0 < NC; c0 += NCH) {
        // stage x chunk (relu applied), 16 channels x 256 pixels, coalesced float4
        #pragma unroll
        for (int i = 0; i < 4; i++) {
            int flat = tid + 256 * i;
            int row = flat >> 6;
            int col4 = flat & 63;
            float4 v = *(const float4*)(xb + (long)(c0 + row) * NP + col4 * 4);
            v.x = fmaxf(v.x, 0.f); v.y = fmaxf(v.y, 0.f);
            v.z = fmaxf(v.z, 0.f); v.w = fmaxf(v.w, 0.f);
            *(float4*)&xs[row][col4 * 4] = v;
        }
        // stage duplicated weights (zero-padded outs 65..71)
        for (int idx = tid; idx < NCH * NOP; idx += 256) {
            int c = idx / NOP;
            int o = idx - c * NOP;
            float v = (o < NO) ? wb[(c0 + c) * NO + o] : 0.f;
            ws[c][o] = make_float2(v, v);
        }
        __syncthreads();

        #pragma unroll
        for (int c = 0; c < NCH; c++) {
            unsigned long long xf[4], wf[9];
            #pragma unroll
            for (int k = 0; k < 4; k++)
                xf[k] = *(const unsigned long long*)&xs[c][2 * (tx + 32 * k)];
            #pragma unroll
            for (int j = 0; j < 9; j++)
                wf[j] = *(const unsigned long long*)&ws[c][ty + 8 * j];
            #pragma unroll
            for (int k = 0; k < 4; k++)
                #pragma unroll
                for (int j = 0; j < 9; j++)
                    asm("fma.rn.f32x2 %0, %1, %2, %0;"
                        : "+l"(acc[k][j]) : "l"(xf[k]), "l"(wf[j]));
        }
        __syncthreads();
    }

    // epilogue: add bias, store unnormalized y into logits layout
    #pragma unroll
    for (int j = 0; j < 9; j++) {
        int o = ty + 8 * j;
        if (o < NO) {
            float bias = b_experts[e * NO + o];
            float* dst = ylog + ((long)b * NO + o) * NP + p0;
            #pragma unroll
            for (int k = 0; k < 4; k++) {
                float2 v = *(float2*)&acc[k][j];
                v.x += bias; v.y += bias;
                *(float2*)(dst + 2 * (tx + 32 * k)) = v;
            }
        }
    }
}

// ---------------- K4a: per (b,o) plane sum / sumsq partials ----------------
__global__ void k4a_stats(const float* __restrict__ ylog) {
    int b = blockIdx.x, o = blockIdx.y;
    const float4* base = (const float4*)(ylog + ((long)b * NO + o) * NP);
    float s = 0.f, q = 0.f;
    #pragma unroll
    for (int i = 0; i < 4; i++) {
        float4 v = base[threadIdx.x + 256 * i];
        s += v.x + v.y + v.z + v.w;
        q += v.x * v.x + v.y * v.y + v.z * v.z + v.w * v.w;
    }
    #pragma unroll
    for (int off = 16; off; off >>= 1) {
        s += __shfl_xor_sync(0xffffffffu, s, off);
        q += __shfl_xor_sync(0xffffffffu, q, off);
    }
    __shared__ float2 red[8];
    if ((threadIdx.x & 31) == 0) red[threadIdx.x >> 5] = make_float2(s, q);
    __syncthreads();
    if (threadIdx.x == 0) {
        float ts = 0.f, tq = 0.f;
        #pragma unroll
        for (int i = 0; i < 8; i++) { ts += red[i].x; tq += red[i].y; }
        g_part[o * NB + b] = make_float2(ts, tq);
    }
}

// ---------------- K4b: finalize BN scale/shift per channel ----------------
__global__ void k4b_finalize(const float* __restrict__ gamma,
                             const float* __restrict__ beta) {
    int o = blockIdx.x;
    int t = threadIdx.x;                          // 64 threads
    float2 v = g_part[o * NB + t];
    float s = v.x, q = v.y;
    #pragma unroll
    for (int off = 16; off; off >>= 1) {
        s += __shfl_xor_sync(0xffffffffu, s, off);
        q += __shfl_xor_sync(0xffffffffu, q, off);
    }
    __shared__ float2 red[2];
    if ((t & 31) == 0) red[t >> 5] = make_float2(s, q);
    __syncthreads();
    if (t == 0) {
        s = red[0].x + red[1].x;
        q = red[0].y + red[1].y;
        const float inv = 1.f / ((float)NB * (float)NP);
        float mean = s * inv;
        float var  = q * inv - mean * mean;
        float sc = gamma[o] * rsqrtf(var + 1e-5f);
        g_scale[o] = sc;
        g_shift[o] = beta[o] - mean * sc;
    }
}

// ---------------- K5: normalize logits in place, softmax, pixel-shuffle prob ----------------
__global__ __launch_bounds__(256) void k5_final(float* __restrict__ ylog,
                                                float* __restrict__ prob) {
    int b = blockIdx.y;
    int h = blockIdx.x * 4 + (threadIdx.x >> 6);
    int w = threadIdx.x & 63;
    long base = ((long)b * NO) * NP + h * NW + w;

    float v[NO];
    float mx = -1e30f;
    #pragma unroll
    for (int o = 0; o < NO; o++) {
        float y = ylog[base + (long)o * NP];
        y = y * g_scale[o] + g_shift[o];
        ylog[base + (long)o * NP] = y;            // final logits
        v[o] = y;
        mx = fmaxf(mx, y);
    }
    float sum = 0.f;
    #pragma unroll
    for (int o = 0; o < NO; o++) {
        float ev = __expf(v[o] - mx);
        v[o] = ev;
        sum += ev;
    }
    float inv = 1.f / sum;

    // prob[b, (h*8+r1)*512 + w*8 + r2] = softmax channel r1*8+r2
    float* pb = prob + (long)b * (512 * 512) + (long)(h * 8) * 512 + w * 8;
    #pragma unroll
    for (int r1 = 0; r1 < 8; r1++) {
        float4 a, c;
        a.x = v[r1 * 8 + 0] * inv; a.y = v[r1 * 8 + 1] * inv;
        a.z = v[r1 * 8 + 2] * inv; a.w = v[r1 * 8 + 3] * inv;
        c.x = v[r1 * 8 + 4] * inv; c.y = v[r1 * 8 + 5] * inv;
        c.z = v[r1 * 8 + 6] * inv; c.w = v[r1 * 8 + 7] * inv;
        *(float4*)(pb + (long)r1 * 512)     = a;
        *(float4*)(pb + (long)r1 * 512 + 4) = c;
    }
}

// ---------------- launch ----------------
extern "C" void kernel_launch(void* const* d_in, const int* in_sizes, int n_in,
                              void* d_out, int out_size) {
    const float* x         = (const float*)d_in[0];
    const float* w_experts = (const float*)d_in[1];
    const float* b_experts = (const float*)d_in[2];
    const float* w_gate    = (const float*)d_in[3];
    const float* b_gate    = (const float*)d_in[4];
    const float* gamma     = (const float*)d_in[5];
    const float* beta      = (const float*)d_in[6];

    float* out  = (float*)d_out;
    float* ylog = out;                                   // logits: B*NO*NP
    float* prob = out + (long)NB * NO * NP;              // prob:   B*512*512
    float* loss = prob + (long)NB * 512 * 512;           // lb_loss scalar

    k1_pool<<<NB * NC, 128>>>(x);
    k2_gate<<<1, 64>>>(w_gate, b_gate, loss);
    k3_gemm<<<dim3(16, NB), 256>>>(x, w_experts, b_experts, ylog);
    k4a_stats<<<dim3(NB, NO), 256>>>(ylog);
    k4b_finalize<<<NO, 64>>>(gamma, beta);
    k5_final<<<dim3(16, NB), 256>>>(ylog, prob);
}

// round 3
// speedup vs baseline: 1.0050x; 1.0050x over previous
#include <cuda_runtime.h>

#define NB   64
#define NC   256
#define NH   64
#define NW   64
#define NP   4096        // H*W
#define NE   4
#define NO   65          // OUT = CELL*CELL+1
#define NOP  72          // padded OUT (multiple of 8)
#define NCH  16          // C chunk for GEMM smem

// ---------------- device scratch (no allocations allowed) ----------------
__device__ float  g_pooled[NB * NC];
__device__ int    g_idx[NB];
__device__ float2 g_part[NO * NB];
__device__ float  g_scale[NO];
__device__ float  g_shift[NO];

// ---------------- K1: pooled[b][c] = mean over pixels of relu(x) ----------------
__global__ void k1_pool(const float* __restrict__ x) {
    int plane = blockIdx.x;                       // b*NC + c
    const float4* base = (const float4*)(x + (long)plane * NP);
    float s = 0.f;
    #pragma unroll
    for (int i = 0; i < 8; i++) {
        float4 v = base[threadIdx.x + 128 * i];
        s += fmaxf(v.x, 0.f) + fmaxf(v.y, 0.f) + fmaxf(v.z, 0.f) + fmaxf(v.w, 0.f);
    }
    #pragma unroll
    for (int o = 16; o; o >>= 1) s += __shfl_xor_sync(0xffffffffu, s, o);
    __shared__ float red[4];
    if ((threadIdx.x & 31) == 0) red[threadIdx.x >> 5] = s;
    __syncthreads();
    if (threadIdx.x == 0)
        g_pooled[plane] = (red[0] + red[1] + red[2] + red[3]) * (1.f / NP);
}

// ---------------- K2: gate logits -> argmax expert, lb_loss ----------------
__global__ void k2_gate(const float* __restrict__ w_gate,
                        const float* __restrict__ b_gate,
                        float* __restrict__ loss_out) {
    int b = threadIdx.x;                          // 64 threads
    float lg[NE];
    #pragma unroll
    for (int e = 0; e < NE; e++) lg[e] = b_gate[e];
    const float* pr = g_pooled + b * NC;
    for (int c = 0; c < NC; c++) {
        float pv = pr[c];
        #pragma unroll
        for (int e = 0; e < NE; e++) lg[e] += pv * w_gate[c * NE + e];
    }
    int best = 0; float bv = lg[0];
    #pragma unroll
    for (int e = 1; e < NE; e++)
        if (lg[e] > bv) { bv = lg[e]; best = e; }   // first max on ties, like argmax
    g_idx[b] = best;

    __shared__ int sidx[NB];
    sidx[b] = best;
    __syncthreads();
    if (b == 0) {
        int cnt[NE] = {0, 0, 0, 0};
        for (int i = 0; i < NB; i++) cnt[sidx[i]]++;
        float u[NE]; float s = 0.f;
        #pragma unroll
        for (int e = 0; e < NE; e++) { u[e] = (float)cnt[e] / (float)NB + 1e-6f; s += u[e]; }
        float lb = 0.f;
        #pragma unroll
        for (int e = 0; e < NE; e++) {
            float uu = u[e] / s;
            lb += uu * (logf(uu) - logf(0.25f));
        }
        loss_out[0] = lb;
    }
}

// ---------------- K3: per-batch expert GEMM with packed f32x2 FMA ----------------
// y[b][o][p] = sum_c relu(x[b][c][p]) * W[e][c][o] + bias[e][o]  (unnormalized, written to logits region)
__global__ __launch_bounds__(256, 2) void k3_gemm(
    const float* __restrict__ x,
    const float* __restrict__ w_experts,
    const float* __restrict__ b_experts,
    float* __restrict__ ylog) {
    __shared__ float  xs[NCH][256];
    __shared__ float2 ws[NCH][NOP];   // weight duplicated into both f32x2 halves

    int b  = blockIdx.y;
    int p0 = blockIdx.x * 256;
    int tid = threadIdx.x;
    int tx = tid & 31;                // lane -> pixel pairs
    int ty = tid >> 5;                // warp -> out group (constant across warp -> broadcast LDS)
    int e = g_idx[b];

    const float* xb = x + ((long)b * NC) * NP + p0;
    const float* wb = w_experts + (long)e * NC * NO;

    unsigned long long acc[4][9];
    #pragma unroll
    for (int k = 0; k < 4; k++)
        #pragma unroll
        for (int j = 0; j < 9; j++) acc[k][j] = 0ull;

    for (int c0 = 0; c0 < NC; c0 += NCH) {
        // stage x chunk (relu applied), 16 channels x 256 pixels, coalesced float4
        #pragma unroll
        for (int i = 0; i < 4; i++) {
            int flat = tid + 256 * i;
            int row = flat >> 6;
            int col4 = flat & 63;
            float4 v = *(const float4*)(xb + (long)(c0 + row) * NP + col4 * 4);
            v.x = fmaxf(v.x, 0.f); v.y = fmaxf(v.y, 0.f);
            v.z = fmaxf(v.z, 0.f); v.w = fmaxf(v.w, 0.f);
            *(float4*)&xs[row][col4 * 4] = v;
        }
        // stage duplicated weights (zero-padded outs 65..71)
        for (int idx = tid; idx < NCH * NOP; idx += 256) {
            int c = idx / NOP;
            int o = idx - c * NOP;
            float v = (o < NO) ? wb[(c0 + c) * NO + o] : 0.f;
            ws[c][o] = make_float2(v, v);
        }
        __syncthreads();

        #pragma unroll
        for (int c = 0; c < NCH; c++) {
            unsigned long long xf[4], wf[9];
            #pragma unroll
            for (int k = 0; k < 4; k++)
                xf[k] = *(const unsigned long long*)&xs[c][2 * (tx + 32 * k)];
            #pragma unroll
            for (int j = 0; j < 9; j++)
                wf[j] = *(const unsigned long long*)&ws[c][ty + 8 * j];
            #pragma unroll
            for (int k = 0; k < 4; k++)
                #pragma unroll
                for (int j = 0; j < 9; j++)
                    asm("fma.rn.f32x2 %0, %1, %2, %0;"
                        : "+l"(acc[k][j]) : "l"(xf[k]), "l"(wf[j]));
        }
        __syncthreads();
    }

    // epilogue: add bias, store unnormalized y into logits layout
    #pragma unroll
    for (int j = 0; j < 9; j++) {
        int o = ty + 8 * j;
        if (o < NO) {
            float bias = b_experts[e * NO + o];
            float* dst = ylog + ((long)b * NO + o) * NP + p0;
            #pragma unroll
            for (int k = 0; k < 4; k++) {
                float2 v = *(float2*)&acc[k][j];
                v.x += bias; v.y += bias;
                *(float2*)(dst + 2 * (tx + 32 * k)) = v;
            }
        }
    }
}

// ---------------- K4a: per (b,o) plane sum / sumsq partials ----------------
__global__ void k4a_stats(const float* __restrict__ ylog) {
    int b = blockIdx.x, o = blockIdx.y;
    const float4* base = (const float4*)(ylog + ((long)b * NO + o) * NP);
    float s = 0.f, q = 0.f;
    #pragma unroll
    for (int i = 0; i < 4; i++) {
        float4 v = base[threadIdx.x + 256 * i];
        s += v.x + v.y + v.z + v.w;
        q += v.x * v.x + v.y * v.y + v.z * v.z + v.w * v.w;
    }
    #pragma unroll
    for (int off = 16; off; off >>= 1) {
        s += __shfl_xor_sync(0xffffffffu, s, off);
        q += __shfl_xor_sync(0xffffffffu, q, off);
    }
    __shared__ float2 red[8];
    if ((threadIdx.x & 31) == 0) red[threadIdx.x >> 5] = make_float2(s, q);
    __syncthreads();
    if (threadIdx.x == 0) {
        float ts = 0.f, tq = 0.f;
        #pragma unroll
        for (int i = 0; i < 8; i++) { ts += red[i].x; tq += red[i].y; }
        g_part[o * NB + b] = make_float2(ts, tq);
    }
}

// ---------------- K4b: finalize BN scale/shift per channel ----------------
__global__ void k4b_finalize(const float* __restrict__ gamma,
                             const float* __restrict__ beta) {
    int o = blockIdx.x;
    int t = threadIdx.x;                          // 64 threads
    float2 v = g_part[o * NB + t];
    float s = v.x, q = v.y;
    #pragma unroll
    for (int off = 16; off; off >>= 1) {
        s += __shfl_xor_sync(0xffffffffu, s, off);
        q += __shfl_xor_sync(0xffffffffu, q, off);
    }
    __shared__ float2 red[2];
    if ((t & 31) == 0) red[t >> 5] = make_float2(s, q);
    __syncthreads();
    if (t == 0) {
        s = red[0].x + red[1].x;
        q = red[0].y + red[1].y;
        const float inv = 1.f / ((float)NB * (float)NP);
        float mean = s * inv;
        float var  = q * inv - mean * mean;
        float sc = gamma[o] * rsqrtf(var + 1e-5f);
        g_scale[o] = sc;
        g_shift[o] = beta[o] - mean * sc;
    }
}

// ---------------- K5: normalize logits in place, softmax, pixel-shuffle prob ----------------
__global__ __launch_bounds__(256) void k5_final(float* __restrict__ ylog,
                                                float* __restrict__ prob) {
    int b = blockIdx.y;
    int h = blockIdx.x * 4 + (threadIdx.x >> 6);
    int w = threadIdx.x & 63;
    long base = ((long)b * NO) * NP + h * NW + w;

    float v[NO];
    float mx = -1e30f;
    #pragma unroll
    for (int o = 0; o < NO; o++) {
        float y = ylog[base + (long)o * NP];
        y = y * g_scale[o] + g_shift[o];
        ylog[base + (long)o * NP] = y;            // final logits
        v[o] = y;
        mx = fmaxf(mx, y);
    }
    float sum = 0.f;
    #pragma unroll
    for (int o = 0; o < NO; o++) {
        float ev = __expf(v[o] - mx);
        v[o] = ev;
        sum += ev;
    }
    float inv = 1.f / sum;

    // prob[b, (h*8+r1)*512 + w*8 + r2] = softmax channel r1*8+r2
    float* pb = prob + (long)b * (512 * 512) + (long)(h * 8) * 512 + w * 8;
    #pragma unroll
    for (int r1 = 0; r1 < 8; r1++) {
        float4 a, c;
        a.x = v[r1 * 8 + 0] * inv; a.y = v[r1 * 8 + 1] * inv;
        a.z = v[r1 * 8 + 2] * inv; a.w = v[r1 * 8 + 3] * inv;
        c.x = v[r1 * 8 + 4] * inv; c.y = v[r1 * 8 + 5] * inv;
        c.z = v[r1 * 8 + 6] * inv; c.w = v[r1 * 8 + 7] * inv;
        *(float4*)(pb + (long)r1 * 512)     = a;
        *(float4*)(pb + (long)r1 * 512 + 4) = c;
    }
}

// ---------------- launch ----------------
extern "C" void kernel_launch(void* const* d_in, const int* in_sizes, int n_in,
                              void* d_out, int out_size) {
    const float* x         = (const float*)d_in[0];
    const float* w_experts = (const float*)d_in[1];
    const float* b_experts = (const float*)d_in[2];
    const float* w_gate    = (const float*)d_in[3];
    const float* b_gate    = (const float*)d_in[4];
    const float* gamma     = (const float*)d_in[5];
    const float* beta      = (const float*)d_in[6];

    float* out  = (float*)d_out;
    float* ylog = out;                                   // logits: B*NO*NP
    float* prob = out + (long)NB * NO * NP;              // prob:   B*512*512
    float* loss = prob + (long)NB * 512 * 512;           // lb_loss scalar

    k1_pool<<<NB * NC, 128>>>(x);
    k2_gate<<<1, 64>>>(w_gate, b_gate, loss);
    k3_gemm<<<dim3(16, NB), 256>>>(x, w_experts, b_experts, ylog);
    k4a_stats<<<dim3(NB, NO), 256>>>(ylog);
    k4b_finalize<<<NO, 64>>>(gamma, beta);
    k5_final<<<dim3(16, NB), 256>>>(ylog, prob);
}

// round 8
// speedup vs baseline: 1.5056x; 1.4981x over previous
#include <cuda_runtime.h>
#include <cstdint>

#define NB   64
#define NC   256
#define NP   4096        // H*W
#define NE   4
#define NO   65          // OUT = CELL*CELL+1
#define NOP  72          // padded OUT

// ---------------- device scratch ----------------
__device__ float  g_pooled[NB * NC];
__device__ int    g_idx[NB];
__device__ float2 g_part[NO * NB];
__device__ float  g_scale[NO];
__device__ float  g_shift[NO];

// ---------------- helpers ----------------
__device__ __forceinline__ uint32_t f2tf32(float f) {
    uint32_t r;
    asm("cvt.rna.tf32.f32 %0, %1;" : "=r"(r) : "f"(f));
    return r;
}

// D(16x8) += A(16x8,row) * B(8x8,col), tf32 inputs, f32 accum
__device__ __forceinline__ void mma8(float* d, uint2 a02, uint2 a13, uint2 b) {
    asm("mma.sync.aligned.m16n8k8.row.col.f32.tf32.tf32.f32 "
        "{%0,%1,%2,%3}, {%4,%5,%6,%7}, {%8,%9}, {%0,%1,%2,%3};"
        : "+f"(d[0]), "+f"(d[1]), "+f"(d[2]), "+f"(d[3])
        : "r"(a02.x), "r"(a13.x), "r"(a02.y), "r"(a13.y), "r"(b.x), "r"(b.y));
}

// ---------------- K1: pooled[b][c] = mean over pixels of relu(x) ----------------
__global__ void k1_pool(const float* __restrict__ x) {
    int plane = blockIdx.x;
    const float4* base = (const float4*)(x + (long)plane * NP);
    float s = 0.f;
    #pragma unroll
    for (int i = 0; i < 8; i++) {
        float4 v = base[threadIdx.x + 128 * i];
        s += fmaxf(v.x, 0.f) + fmaxf(v.y, 0.f) + fmaxf(v.z, 0.f) + fmaxf(v.w, 0.f);
    }
    #pragma unroll
    for (int o = 16; o; o >>= 1) s += __shfl_xor_sync(0xffffffffu, s, o);
    __shared__ float red[4];
    if ((threadIdx.x & 31) == 0) red[threadIdx.x >> 5] = s;
    __syncthreads();
    if (threadIdx.x == 0)
        g_pooled[plane] = (red[0] + red[1] + red[2] + red[3]) * (1.f / NP);
}

// ---------------- K2: gate -> argmax expert, lb_loss ----------------
__global__ void k2_gate(const float* __restrict__ w_gate,
                        const float* __restrict__ b_gate,
                        float* __restrict__ loss_out) {
    int b = threadIdx.x;                          // 64 threads
    float lg[NE];
    #pragma unroll
    for (int e = 0; e < NE; e++) lg[e] = b_gate[e];
    const float* pr = g_pooled + b * NC;
    for (int c = 0; c < NC; c++) {
        float pv = pr[c];
        #pragma unroll
        for (int e = 0; e < NE; e++) lg[e] += pv * w_gate[c * NE + e];
    }
    int best = 0; float bv = lg[0];
    #pragma unroll
    for (int e = 1; e < NE; e++)
        if (lg[e] > bv) { bv = lg[e]; best = e; }
    g_idx[b] = best;

    __shared__ int sidx[NB];
    sidx[b] = best;
    __syncthreads();
    if (b == 0) {
        int cnt[NE] = {0, 0, 0, 0};
        for (int i = 0; i < NB; i++) cnt[sidx[i]]++;
        float u[NE]; float s = 0.f;
        #pragma unroll
        for (int e = 0; e < NE; e++) { u[e] = (float)cnt[e] / (float)NB + 1e-6f; s += u[e]; }
        float lb = 0.f;
        #pragma unroll
        for (int e = 0; e < NE; e++) {
            float uu = u[e] / s;
            lb += uu * (logf(uu) - logf(0.25f));
        }
        loss_out[0] = lb;
    }
}

// ---------------- K3: expert GEMM via mma.sync tf32 ----------------
// CTA = (pixel tile of 256, batch). D[256 x 72] = relu(x)[256 x 256] * W[e][256 x 72]
#define XS_STR 260     // float2 stride (256 pixels + pad) -> conflict-free frags
#define WS_STR 76      // float2 stride (72 outs + pad)    -> conflict-free frags

__global__ __launch_bounds__(256) void k3_mma(const float* __restrict__ x,
                                              const float* __restrict__ w_experts,
                                              const float* __restrict__ b_experts,
                                              float* __restrict__ ylog) {
    // pair-row r = g*4 + j holds channels (c0 + g*8 + j, c0 + g*8 + j + 4) interleaved
    __shared__ uint2 xs2[16 * XS_STR];
    __shared__ uint2 ws2[16 * WS_STR];
    __shared__ float bias_s[NOP];

    int tid = threadIdx.x;
    int lane = tid & 31, wid = tid >> 5;
    int j = lane & 3, q = lane >> 2;
    int b = blockIdx.y;
    int p0 = blockIdx.x * 256;
    int e = g_idx[b];
    int warp_m = wid * 32;

    const float* xb = x + (size_t)b * NC * NP + p0;
    const float* wb = w_experts + (size_t)e * NC * NO;

    if (tid < NOP) bias_s[tid] = (tid < NO) ? b_experts[e * NO + tid] : 0.f;

    float acc[2][9][4];
    #pragma unroll
    for (int mt = 0; mt < 2; mt++)
        #pragma unroll
        for (int nt = 0; nt < 9; nt++)
            #pragma unroll
            for (int r = 0; r < 4; r++) acc[mt][nt][r] = 0.f;

    for (int c0 = 0; c0 < NC; c0 += 32) {
        // ---- stage x chunk: 32 channels x 256 pixels, relu + tf32, (k,k+4) pairs ----
        {
            int prbase = tid >> 6;          // 0..3
            int p = (tid & 63) * 4;
            #pragma unroll
            for (int it = 0; it < 4; it++) {
                int pr = it * 4 + prbase;   // pair-row 0..15
                int g = pr >> 2, jj = pr & 3;
                const float* lo = xb + (size_t)(c0 + g * 8 + jj) * NP + p;
                float4 vl = *(const float4*)lo;
                float4 vh = *(const float4*)(lo + 4 * (size_t)NP);
                uint2* dst = &xs2[pr * XS_STR + p];
                dst[0] = make_uint2(f2tf32(fmaxf(vl.x, 0.f)), f2tf32(fmaxf(vh.x, 0.f)));
                dst[1] = make_uint2(f2tf32(fmaxf(vl.y, 0.f)), f2tf32(fmaxf(vh.y, 0.f)));
                dst[2] = make_uint2(f2tf32(fmaxf(vl.z, 0.f)), f2tf32(fmaxf(vh.z, 0.f)));
                dst[3] = make_uint2(f2tf32(fmaxf(vl.w, 0.f)), f2tf32(fmaxf(vh.w, 0.f)));
            }
        }
        // ---- stage w chunk: 32 channels x 72 outs (zero-padded), (k,k+4) pairs ----
        for (int i = tid; i < 16 * NOP; i += 256) {
            int r = i / NOP;
            int n = i - r * NOP;
            int g = r >> 2, jj = r & 3;
            int klo = c0 + g * 8 + jj;
            float lo = (n < NO) ? wb[(size_t)klo * NO + n] : 0.f;
            float hi = (n < NO) ? wb[(size_t)(klo + 4) * NO + n] : 0.f;
            ws2[r * WS_STR + n] = make_uint2(f2tf32(lo), f2tf32(hi));
        }
        __syncthreads();

        #pragma unroll
        for (int g = 0; g < 4; g++) {
            const uint2* xrow = &xs2[(g * 4 + j) * XS_STR + warp_m];
            uint2 a00 = xrow[q];
            uint2 a01 = xrow[q + 8];
            uint2 a10 = xrow[16 + q];
            uint2 a11 = xrow[16 + q + 8];
            const uint2* wrow = &ws2[(g * 4 + j) * WS_STR + q];
            #pragma unroll
            for (int nt = 0; nt < 9; nt++) {
                uint2 bb = wrow[nt * 8];
                mma8(acc[0][nt], a00, a01, bb);
                mma8(acc[1][nt], a10, a11, bb);
            }
        }
        __syncthreads();
    }

    // ---- epilogue: add bias, store ----
    #pragma unroll
    for (int mt = 0; mt < 2; mt++) {
        int prow = p0 + warp_m + mt * 16 + q;
        #pragma unroll
        for (int nt = 0; nt < 9; nt++) {
            int o0 = nt * 8 + 2 * j;
            if (o0 < NO) {
                float bias = bias_s[o0];
                float* d = ylog + ((size_t)b * NO + o0) * NP + prow;
                d[0] = acc[mt][nt][0] + bias;
                d[8] = acc[mt][nt][2] + bias;
            }
            if (o0 + 1 < NO) {
                float bias = bias_s[o0 + 1];
                float* d = ylog + ((size_t)b * NO + o0 + 1) * NP + prow;
                d[0] = acc[mt][nt][1] + bias;
                d[8] = acc[mt][nt][3] + bias;
            }
        }
    }
}

// ---------------- K4a: per (b,o) plane sum / sumsq partials ----------------
__global__ void k4a_stats(const float* __restrict__ ylog) {
    int b = blockIdx.x, o = blockIdx.y;
    const float4* base = (const float4*)(ylog + ((long)b * NO + o) * NP);
    float s = 0.f, qq = 0.f;
    #pragma unroll
    for (int i = 0; i < 4; i++) {
        float4 v = base[threadIdx.x + 256 * i];
        s += v.x + v.y + v.z + v.w;
        qq += v.x * v.x + v.y * v.y + v.z * v.z + v.w * v.w;
    }
    #pragma unroll
    for (int off = 16; off; off >>= 1) {
        s  += __shfl_xor_sync(0xffffffffu, s, off);
        qq += __shfl_xor_sync(0xffffffffu, qq, off);
    }
    __shared__ float2 red[8];
    if ((threadIdx.x & 31) == 0) red[threadIdx.x >> 5] = make_float2(s, qq);
    __syncthreads();
    if (threadIdx.x == 0) {
        float ts = 0.f, tq = 0.f;
        #pragma unroll
        for (int i = 0; i < 8; i++) { ts += red[i].x; tq += red[i].y; }
        g_part[o * NB + b] = make_float2(ts, tq);
    }
}

// ---------------- K4b: finalize BN scale/shift per channel ----------------
__global__ void k4b_finalize(const float* __restrict__ gamma,
                             const float* __restrict__ beta) {
    int o = blockIdx.x;
    int t = threadIdx.x;
    float2 v = g_part[o * NB + t];
    float s = v.x, qq = v.y;
    #pragma unroll
    for (int off = 16; off; off >>= 1) {
        s  += __shfl_xor_sync(0xffffffffu, s, off);
        qq += __shfl_xor_sync(0xffffffffu, qq, off);
    }
    __shared__ float2 red[2];
    if ((t & 31) == 0) red[t >> 5] = make_float2(s, qq);
    __syncthreads();
    if (t == 0) {
        s = red[0].x + red[1].x;
        qq = red[0].y + red[1].y;
        const float inv = 1.f / ((float)NB * (float)NP);
        float mean = s * inv;
        float var = qq * inv - mean * mean;
        float sc = gamma[o] * rsqrtf(var + 1e-5f);
        g_scale[o] = sc;
        g_shift[o] = beta[o] - mean * sc;
    }
}

// ---------------- K5: normalize logits, softmax, pixel-shuffle prob ----------------
__global__ __launch_bounds__(256) void k5_final(float* __restrict__ ylog,
                                                float* __restrict__ prob) {
    int b = blockIdx.y;
    int h = blockIdx.x * 4 + (threadIdx.x >> 6);
    int w = threadIdx.x & 63;
    long base = ((long)b * NO) * NP + h * 64 + w;

    float v[NO];
    float mx = -1e30f;
    #pragma unroll
    for (int o = 0; o < NO; o++) {
        float y = ylog[base + (long)o * NP];
        y = y * g_scale[o] + g_shift[o];
        ylog[base + (long)o * NP] = y;
        v[o] = y;
        mx = fmaxf(mx, y);
    }
    float sum = 0.f;
    #pragma unroll
    for (int o = 0; o < NO; o++) {
        float ev = __expf(v[o] - mx);
        v[o] = ev;
        sum += ev;
    }
    float inv = 1.f / sum;

    float* pb = prob + (long)b * (512 * 512) + (long)(h * 8) * 512 + w * 8;
    #pragma unroll
    for (int r1 = 0; r1 < 8; r1++) {
        float4 a, c;
        a.x = v[r1 * 8 + 0] * inv; a.y = v[r1 * 8 + 1] * inv;
        a.z = v[r1 * 8 + 2] * inv; a.w = v[r1 * 8 + 3] * inv;
        c.x = v[r1 * 8 + 4] * inv; c.y = v[r1 * 8 + 5] * inv;
        c.z = v[r1 * 8 + 6] * inv; c.w = v[r1 * 8 + 7] * inv;
        *(float4*)(pb + (long)r1 * 512)     = a;
        *(float4*)(pb + (long)r1 * 512 + 4) = c;
    }
}

// ---------------- launch ----------------
extern "C" void kernel_launch(void* const* d_in, const int* in_sizes, int n_in,
                              void* d_out, int out_size) {
    const float* x         = (const float*)d_in[0];
    const float* w_experts = (const float*)d_in[1];
    const float* b_experts = (const float*)d_in[2];
    const float* w_gate    = (const float*)d_in[3];
    const float* b_gate    = (const float*)d_in[4];
    const float* gamma     = (const float*)d_in[5];
    const float* beta      = (const float*)d_in[6];

    float* out  = (float*)d_out;
    float* ylog = out;                              // logits: B*NO*NP
    float* prob = out + (long)NB * NO * NP;         // prob:   B*512*512
    float* loss = prob + (long)NB * 512 * 512;      // lb_loss scalar

    k1_pool<<<NB * NC, 128>>>(x);
    k2_gate<<<1, 64>>>(w_gate, b_gate, loss);
    k3_mma<<<dim3(16, NB), 256>>>(x, w_experts, b_experts, ylog);
    k4a_stats<<<dim3(NB, NO), 256>>>(ylog);
    k4b_finalize<<<NO, 64>>>(gamma, beta);
    k5_final<<<dim3(16, NB), 256>>>(ylog, prob);
}

// round 9
// speedup vs baseline: 2.0161x; 1.3391x over previous
#include <cuda_runtime.h>
#include <cstdint>

#define NB    64
#define NC    256
#define NP    4096        // H*W
#define NE    4
#define NO    65          // OUT = CELL*CELL+1
#define NOP   72          // padded OUT
#define NTILE 16          // 256-pixel tiles per batch

// k3 dynamic smem layout (bytes)
#define XS_STR   264                          // floats per x row (bank spread 8j+q)
#define WS_STR   76                           // uint2 per w row
#define XS_BYTES (32 * XS_STR * 4)            // 33792
#define WS_BYTES (16 * WS_STR * 8)            // 9728
#define OFF_XS0  0
#define OFF_XS1  XS_BYTES
#define OFF_WS0  (2 * XS_BYTES)               // 67584
#define OFF_WS1  (2 * XS_BYTES + WS_BYTES)    // 77312
#define OFF_BIAS (2 * XS_BYTES + 2 * WS_BYTES)// 87040
#define OFF_SRED (OFF_BIAS + 512)             // 87552
#define SMEM_K3  (OFF_SRED + 8 * 72 * 8)      // 92160

// ---------------- device scratch ----------------
__device__ float  g_pooled[NB * NC];
__device__ int    g_idx[NB];
__device__ float2 g_part2[NO * NB * NTILE];
__device__ float  g_scale[NO];
__device__ float  g_shift[NO];
__device__ __align__(16) uint2 g_Wp[NE * 128 * NOP];   // [e][pair-row][n]

// ---------------- helpers ----------------
__device__ __forceinline__ uint32_t f2tf32(float f) {
    uint32_t r;
    asm("cvt.rna.tf32.f32 %0, %1;" : "=r"(r) : "f"(f));
    return r;
}
__device__ __forceinline__ uint32_t smem_u32(const void* p) {
    uint32_t a;
    asm("{ .reg .u64 t; cvta.to.shared.u64 t, %1; cvt.u32.u64 %0, t; }" : "=r"(a) : "l"(p));
    return a;
}
// D(16x8) += A(16x8,row) * B(8x8,col), tf32 inputs, f32 accum
__device__ __forceinline__ void mma8(float* d, uint2 a02, uint2 a13, uint2 b) {
    asm("mma.sync.aligned.m16n8k8.row.col.f32.tf32.tf32.f32 "
        "{%0,%1,%2,%3}, {%4,%5,%6,%7}, {%8,%9}, {%0,%1,%2,%3};"
        : "+f"(d[0]), "+f"(d[1]), "+f"(d[2]), "+f"(d[3])
        : "r"(a02.x), "r"(a13.x), "r"(a02.y), "r"(a13.y), "r"(b.x), "r"(b.y));
}
#define CP16(dst_u32, src_ptr) \
    asm volatile("cp.async.cg.shared.global [%0], [%1], 16;" :: "r"(dst_u32), "l"(src_ptr) : "memory")
#define CP_COMMIT() asm volatile("cp.async.commit_group;" ::: "memory")
#define CP_WAIT(N)  asm volatile("cp.async.wait_group %0;" :: "n"(N) : "memory")

// ---------------- K0: pack W[e] into tf32 (k,k+4)-pair rows ----------------
// pair-row r (0..127): chunk c=r>>4, g=(r>>2)&3, j=r&3 -> channels (c*32+g*8+j, +4)
__global__ void k0_wprep(const float* __restrict__ w) {
    int idx = blockIdx.x * 256 + threadIdx.x;       // NE*128*72 = 36864
    int e = idx / (128 * NOP);
    int rem = idx - e * (128 * NOP);
    int r = rem / NOP;
    int n = rem - r * NOP;
    int c = r >> 4, rr = r & 15;
    int k = c * 32 + (rr >> 2) * 8 + (rr & 3);
    float lo = (n < NO) ? w[(e * NC + k) * NO + n] : 0.f;
    float hi = (n < NO) ? w[(e * NC + k + 4) * NO + n] : 0.f;
    g_Wp[idx] = make_uint2(f2tf32(lo), f2tf32(hi));
}

// ---------------- K1: pooled[b][c] = mean over pixels of relu(x) ----------------
__global__ void k1_pool(const float* __restrict__ x) {
    int plane = blockIdx.x;
    const float4* base = (const float4*)(x + (long)plane * NP);
    float s = 0.f;
    #pragma unroll
    for (int i = 0; i < 8; i++) {
        float4 v = base[threadIdx.x + 128 * i];
        s += fmaxf(v.x, 0.f) + fmaxf(v.y, 0.f) + fmaxf(v.z, 0.f) + fmaxf(v.w, 0.f);
    }
    #pragma unroll
    for (int o = 16; o; o >>= 1) s += __shfl_xor_sync(0xffffffffu, s, o);
    __shared__ float red[4];
    if ((threadIdx.x & 31) == 0) red[threadIdx.x >> 5] = s;
    __syncthreads();
    if (threadIdx.x == 0)
        g_pooled[plane] = (red[0] + red[1] + red[2] + red[3]) * (1.f / NP);
}

// ---------------- K2: gate -> argmax expert, lb_loss ----------------
__global__ void k2_gate(const float* __restrict__ w_gate,
                        const float* __restrict__ b_gate,
                        float* __restrict__ loss_out) {
    int b = threadIdx.x;                          // 64 threads
    float lg[NE];
    #pragma unroll
    for (int e = 0; e < NE; e++) lg[e] = b_gate[e];
    const float* pr = g_pooled + b * NC;
    for (int c = 0; c < NC; c++) {
        float pv = pr[c];
        #pragma unroll
        for (int e = 0; e < NE; e++) lg[e] += pv * w_gate[c * NE + e];
    }
    int best = 0; float bv = lg[0];
    #pragma unroll
    for (int e = 1; e < NE; e++)
        if (lg[e] > bv) { bv = lg[e]; best = e; }
    g_idx[b] = best;

    __shared__ int sidx[NB];
    sidx[b] = best;
    __syncthreads();
    if (b == 0) {
        int cnt[NE] = {0, 0, 0, 0};
        for (int i = 0; i < NB; i++) cnt[sidx[i]]++;
        float u[NE]; float s = 0.f;
        #pragma unroll
        for (int e = 0; e < NE; e++) { u[e] = (float)cnt[e] / (float)NB + 1e-6f; s += u[e]; }
        float lb = 0.f;
        #pragma unroll
        for (int e = 0; e < NE; e++) {
            float uu = u[e] / s;
            lb += uu * (logf(uu) - logf(0.25f));
        }
        loss_out[0] = lb;
    }
}

// ---------------- K3: cp.async-pipelined tf32 GEMM + fused BN partials ----------------
#define ISSUE(c, XOFF, WOFF) do { \
    const float* _xsrc = xsrc_base + (size_t)(c) * 32 * NP; \
    uint32_t _xdst = sbase + (XOFF) + xrow * (XS_STR * 4) + xcol * 16; \
    _Pragma("unroll") \
    for (int _i = 0; _i < 8; _i++) \
        CP16(_xdst + _i * 128, _xsrc + _i * 32); \
    _Pragma("unroll") \
    for (int _it = 0; _it < 3; _it++) { \
        int _ii = tid + _it * 256; \
        if (_ii < 576) { \
            int _r = _ii / 36, _cc = _ii - _r * 36; \
            CP16(sbase + (WOFF) + _r * (WS_STR * 8) + _cc * 16, \
                 (const char*)(wp + ((c) * 16 + _r) * NOP + _cc * 2)); \
        } \
    } \
    CP_COMMIT(); \
} while (0)

#define MMACHUNK(XOFF, WOFF) do { \
    const float* _xsr = (const float*)(sm + (XOFF)); \
    const uint2* _wsp = (const uint2*)(sm + (WOFF)); \
    _Pragma("unroll") \
    for (int _g = 0; _g < 4; _g++) { \
        const float* _xj = _xsr + (_g * 8 + j) * XS_STR + warp_m; \
        uint2 a00, a01, a10, a11; \
        a00.x = f2tf32(fmaxf(_xj[q],      0.f)); a00.y = f2tf32(fmaxf(_xj[4 * XS_STR + q],      0.f)); \
        a01.x = f2tf32(fmaxf(_xj[q + 8],  0.f)); a01.y = f2tf32(fmaxf(_xj[4 * XS_STR + q + 8],  0.f)); \
        a10.x = f2tf32(fmaxf(_xj[q + 16], 0.f)); a10.y = f2tf32(fmaxf(_xj[4 * XS_STR + q + 16], 0.f)); \
        a11.x = f2tf32(fmaxf(_xj[q + 24], 0.f)); a11.y = f2tf32(fmaxf(_xj[4 * XS_STR + q + 24], 0.f)); \
        const uint2* _wrow = _wsp + (_g * 4 + j) * WS_STR + q; \
        _Pragma("unroll") \
        for (int _nt = 0; _nt < 9; _nt++) { \
            uint2 _bb = _wrow[_nt * 8]; \
            mma8(acc[0][_nt], a00, a01, _bb); \
            mma8(acc[1][_nt], a10, a11, _bb); \
        } \
    } \
} while (0)

__global__ __launch_bounds__(256, 2) void k3_mma(const float* __restrict__ x,
                                                 const float* __restrict__ b_experts,
                                                 float* __restrict__ ylog) {
    extern __shared__ __align__(16) char sm[];
    float*  bias_s = (float*)(sm + OFF_BIAS);
    float2* sred   = (float2*)(sm + OFF_SRED);
    uint32_t sbase = smem_u32(sm);

    int tid = threadIdx.x, lane = tid & 31, wid = tid >> 5;
    int j = lane & 3, q = lane >> 2;
    int b = blockIdx.y, tile = blockIdx.x;
    int p0 = tile * 256;
    int e = g_idx[b];
    int warp_m = wid * 32;

    const float* xb = x + (size_t)b * NC * NP + p0;
    const uint2* wp = g_Wp + e * (128 * NOP);

    if (tid < NOP) bias_s[tid] = (tid < NO) ? b_experts[e * NO + tid] : 0.f;

    // cp.async x mapping: 32 rows x 64 float4; 8 threads/row, 8 iters
    int xrow = tid >> 3;
    int xcol = tid & 7;
    const float* xsrc_base = xb + (size_t)xrow * NP + xcol * 4;

    float acc[2][9][4];
    #pragma unroll
    for (int mt = 0; mt < 2; mt++)
        #pragma unroll
        for (int nt = 0; nt < 9; nt++)
            #pragma unroll
            for (int r = 0; r < 4; r++) acc[mt][nt][r] = 0.f;

    ISSUE(0, OFF_XS0, OFF_WS0);

    for (int cc = 0; cc < 4; cc++) {
        int ce = 2 * cc;                 // even chunk -> buffer 0 (ce <= 6, always prefetch)
        ISSUE(ce + 1, OFF_XS1, OFF_WS1);
        CP_WAIT(1);
        __syncthreads();
        MMACHUNK(OFF_XS0, OFF_WS0);
        __syncthreads();

        int co = ce + 1;                 // odd chunk -> buffer 1
        if (co < 7) {
            ISSUE(co + 1, OFF_XS0, OFF_WS0);
            CP_WAIT(1);
        } else {
            CP_WAIT(0);
        }
        __syncthreads();
        MMACHUNK(OFF_XS1, OFF_WS1);
        __syncthreads();
    }

    // ---- epilogue: bias, store y, fused per-channel sum/sumsq partials ----
    float sE[9], qE[9], sO[9], qO[9];
    int prow = p0 + warp_m + q;
    #pragma unroll
    for (int nt = 0; nt < 9; nt++) {
        int o0 = nt * 8 + 2 * j;
        float b0 = bias_s[o0], b1 = bias_s[o0 + 1];
        float v00 = acc[0][nt][0] + b0, v02 = acc[0][nt][2] + b0;
        float v10 = acc[1][nt][0] + b0, v12 = acc[1][nt][2] + b0;
        float v01 = acc[0][nt][1] + b1, v03 = acc[0][nt][3] + b1;
        float v11 = acc[1][nt][1] + b1, v13 = acc[1][nt][3] + b1;
        if (o0 < NO) {
            float* d = ylog + ((size_t)b * NO + o0) * NP + prow;
            d[0] = v00; d[8] = v02; d[16] = v10; d[24] = v12;
        }
        if (o0 + 1 < NO) {
            float* d = ylog + ((size_t)b * NO + o0 + 1) * NP + prow;
            d[0] = v01; d[8] = v03; d[16] = v11; d[24] = v13;
        }
        sE[nt] = v00 + v02 + v10 + v12;
        qE[nt] = v00 * v00 + v02 * v02 + v10 * v10 + v12 * v12;
        sO[nt] = v01 + v03 + v11 + v13;
        qO[nt] = v01 * v01 + v03 * v03 + v11 * v11 + v13 * v13;
    }
    #pragma unroll
    for (int nt = 0; nt < 9; nt++) {
        #pragma unroll
        for (int off = 4; off < 32; off <<= 1) {
            sE[nt] += __shfl_xor_sync(0xffffffffu, sE[nt], off);
            qE[nt] += __shfl_xor_sync(0xffffffffu, qE[nt], off);
            sO[nt] += __shfl_xor_sync(0xffffffffu, sO[nt], off);
            qO[nt] += __shfl_xor_sync(0xffffffffu, qO[nt], off);
        }
    }
    if (q == 0) {        // lanes 0..3 hold warp totals for cols 2j / 2j+1 of each nt
        #pragma unroll
        for (int nt = 0; nt < 9; nt++) {
            sred[wid * NOP + nt * 8 + 2 * j]     = make_float2(sE[nt], qE[nt]);
            sred[wid * NOP + nt * 8 + 2 * j + 1] = make_float2(sO[nt], qO[nt]);
        }
    }
    __syncthreads();
    if (tid < NO) {
        float ts = 0.f, tq = 0.f;
        #pragma unroll
        for (int w = 0; w < 8; w++) {
            float2 v = sred[w * NOP + tid];
            ts += v.x; tq += v.y;
        }
        g_part2[tid * (NB * NTILE) + b * NTILE + tile] = make_float2(ts, tq);
    }
}

// ---------------- K4b: reduce partials, finalize BN scale/shift ----------------
__global__ void k4b_finalize(const float* __restrict__ gamma,
                             const float* __restrict__ beta) {
    int o = blockIdx.x;
    int t = threadIdx.x;                 // 256
    const float2* p = g_part2 + o * (NB * NTILE);
    float s = 0.f, qq = 0.f;
    #pragma unroll
    for (int i = 0; i < 4; i++) {
        float2 v = p[t + 256 * i];
        s += v.x; qq += v.y;
    }
    #pragma unroll
    for (int off = 16; off; off >>= 1) {
        s  += __shfl_xor_sync(0xffffffffu, s, off);
        qq += __shfl_xor_sync(0xffffffffu, qq, off);
    }
    __shared__ float2 red[8];
    if ((t & 31) == 0) red[t >> 5] = make_float2(s, qq);
    __syncthreads();
    if (t == 0) {
        float ts = 0.f, tq = 0.f;
        #pragma unroll
        for (int i = 0; i < 8; i++) { ts += red[i].x; tq += red[i].y; }
        const float inv = 1.f / ((float)NB * (float)NP);
        float mean = ts * inv;
        float var = tq * inv - mean * mean;
        float sc = gamma[o] * rsqrtf(var + 1e-5f);
        g_scale[o] = sc;
        g_shift[o] = beta[o] - mean * sc;
    }
}

// ---------------- K5: normalize logits, softmax, pixel-shuffle prob ----------------
__global__ __launch_bounds__(256) void k5_final(float* __restrict__ ylog,
                                                float* __restrict__ prob) {
    int b = blockIdx.y;
    int h = blockIdx.x * 4 + (threadIdx.x >> 6);
    int w = threadIdx.x & 63;
    long base = ((long)b * NO) * NP + h * 64 + w;

    float v[NO];
    float mx = -1e30f;
    #pragma unroll
    for (int o = 0; o < NO; o++) {
        float y = ylog[base + (long)o * NP];
        y = y * g_scale[o] + g_shift[o];
        ylog[base + (long)o * NP] = y;
        v[o] = y;
        mx = fmaxf(mx, y);
    }
    float sum = 0.f;
    #pragma unroll
    for (int o = 0; o < NO; o++) {
        float ev = __expf(v[o] - mx);
        v[o] = ev;
        sum += ev;
    }
    float inv = 1.f / sum;

    float* pb = prob + (long)b * (512 * 512) + (long)(h * 8) * 512 + w * 8;
    #pragma unroll
    for (int r1 = 0; r1 < 8; r1++) {
        float4 a, c;
        a.x = v[r1 * 8 + 0] * inv; a.y = v[r1 * 8 + 1] * inv;
        a.z = v[r1 * 8 + 2] * inv; a.w = v[r1 * 8 + 3] * inv;
        c.x = v[r1 * 8 + 4] * inv; c.y = v[r1 * 8 + 5] * inv;
        c.z = v[r1 * 8 + 6] * inv; c.w = v[r1 * 8 + 7] * inv;
        *(float4*)(pb + (long)r1 * 512)     = a;
        *(float4*)(pb + (long)r1 * 512 + 4) = c;
    }
}

// ---------------- launch ----------------
extern "C" void kernel_launch(void* const* d_in, const int* in_sizes, int n_in,
                              void* d_out, int out_size) {
    const float* x         = (const float*)d_in[0];
    const float* w_experts = (const float*)d_in[1];
    const float* b_experts = (const float*)d_in[2];
    const float* w_gate    = (const float*)d_in[3];
    const float* b_gate    = (const float*)d_in[4];
    const float* gamma     = (const float*)d_in[5];
    const float* beta      = (const float*)d_in[6];

    float* out  = (float*)d_out;
    float* ylog = out;                              // logits: B*NO*NP
    float* prob = out + (long)NB * NO * NP;         // prob:   B*512*512
    float* loss = prob + (long)NB * 512 * 512;      // lb_loss scalar

    cudaFuncSetAttribute(k3_mma, cudaFuncAttributeMaxDynamicSharedMemorySize, SMEM_K3);

    k0_wprep<<<144, 256>>>(w_experts);
    k1_pool<<<NB * NC, 128>>>(x);
    k2_gate<<<1, 64>>>(w_gate, b_gate, loss);
    k3_mma<<<dim3(NTILE, NB), 256, SMEM_K3>>>(x, b_experts, ylog);
    k4b_finalize<<<NO, 256>>>(gamma, beta);
    k5_final<<<dim3(16, NB), 256>>>(ylog, prob);
}